// round 15
// baseline (speedup 1.0000x reference)
#include <cuda_runtime.h>
#include <cuda_fp16.h>
#include <cstdint>

// ---------------------------------------------------------------------------
// LSTM_41764261986630 : 2-layer LSTM, T=512, B=64, IN=H=512
// mma.sync (HMMA) single-term fp16, persistent, weight-stationary.
// R14: (1) A fragments packed in kstep PAIRS -> LDG.128 (half the LDG count)
//      (2) per-layer 64-CTA team barriers; g_h0 full T-depth so team0 never
//          waits on team1 (no backward edge; unlike failed R11).
// ---------------------------------------------------------------------------

#define TSTEPS 512
#define BATCH  64
#define HID    512
#define BH     (BATCH*HID)
#define NCTA   128
#define NTHR   256

// SMEM byte offsets
#define SO_W    0          // 65536 B : [tile 0..127][256 fp16]
#define SO_RED  65536      // 4*32*17*4 = 8704 B partial-D staging
#define SO_BIAS 74240      // 32 floats
#define SMEM_TOTAL 74368

// ---- persistent device scratch (no cudaMalloc allowed) ----
__device__ __align__(16) __half g_w[(size_t)NCTA*128*256];          // 8MB
__device__ __align__(16) __half g_x[(size_t)TSTEPS*32768];          // 32MB
__device__ __align__(16) __half g_h0[(size_t)TSTEPS*32768];         // 32MB full depth
__device__ __align__(16) __half g_h1[2*32768];
__device__ unsigned g_bar;
__device__ unsigned g_done0, g_done1;    // per-team wave counters

// ---------------- helpers ----------------
__device__ __forceinline__ void cp_async16(void* sdst, const void* gsrc) {
    unsigned sa;
    asm("{ .reg .u64 t; cvta.to.shared.u64 t, %1; cvt.u32.u64 %0, t; }"
        : "=r"(sa) : "l"(sdst));
    asm volatile("cp.async.cg.shared.global [%0], [%1], 16;\n" :: "r"(sa), "l"(gsrc));
}
#define CP_COMMIT() asm volatile("cp.async.commit_group;\n")
#define CP_WAIT(n)  asm volatile("cp.async.wait_group %0;\n" :: "n"(n))

__device__ __forceinline__ void mma16816(float* d,
        uint32_t a0, uint32_t a1, uint32_t a2, uint32_t a3,
        uint32_t b0, uint32_t b1) {
    asm volatile(
      "mma.sync.aligned.m16n8k16.row.col.f32.f16.f16.f32 "
      "{%0,%1,%2,%3}, {%4,%5,%6,%7}, {%8,%9}, {%0,%1,%2,%3};"
      : "+f"(d[0]), "+f"(d[1]), "+f"(d[2]), "+f"(d[3])
      : "r"(a0), "r"(a1), "r"(a2), "r"(a3), "r"(b0), "r"(b1));
}

// fragment-order position of k-local element within a 16-wide act row
__device__ __host__ __forceinline__ int p_of_kl(int kl) {
    return ((kl & 7) >> 1) * 4 + ((kl >> 3) << 1) + (kl & 1);
}

// final full-grid barrier (monotonic counter: safe across graph replays)
__device__ __forceinline__ void grid_sync() {
    __threadfence();
    __syncthreads();
    if (threadIdx.x == 0) {
        unsigned arrive = atomicAdd(&g_bar, 1u);
        unsigned target = (arrive / NCTA + 1u) * NCTA;
        while (*(volatile unsigned*)&g_bar < target) { }
        __threadfence();
    }
    __syncthreads();
}

// ---------------- prep kernels ----------------
// W fragment image per CTA: [tile ti = s*2+mb][lane L][8 fp16]
__global__ void prep_w(const float* __restrict__ Wx, const float* __restrict__ Wh) {
    const int blk = blockIdx.x;               // cta*8 + ch
    const int ch = blk & 7, cta = blk >> 3;
    const int layer = cta >> 6, hb = cta & 63;
    const float* wx = Wx + (size_t)layer * 2048 * 512;
    const float* wh = Wh + (size_t)layer * 2048 * 512;
    const size_t base = (size_t)cta * 128 * 256;
    for (int e = threadIdx.x; e < 16 * 256; e += blockDim.x) {
        int ti  = ch * 16 + (e >> 8);
        int q16 = e & 255;
        int L = q16 >> 3, eb = q16 & 7;
        int qreg = eb >> 1, half = eb & 1;
        int s = ti >> 1, mb = ti & 1;
        int m  = (L >> 2) + ((qreg & 1) << 3) + (mb << 4);   // row 0..31
        int kl = ((L & 3) << 1) + ((qreg >> 1) << 3) + half;
        int k  = (s << 4) + kl;
        int R  = (m >> 3) * 512 + hb * 8 + (m & 7);
        float v = (k < 512) ? wx[(size_t)R * 512 + k]
                            : wh[(size_t)R * 512 + (k - 512)];
        g_w[base + (size_t)ti * 256 + q16] = __float2half_rn(v);
    }
}

// x fragment image, PAIRED layout:
// [t][pair P 0..15][n 0..63][lane-quad 0..3][sp 0..1][half 0..3]
__global__ void prep_x(const float* __restrict__ x) {
    const int t = blockIdx.x;
    const float* src = x + (size_t)t * BH;
    const size_t dst = (size_t)t * 32768;
    for (int e = threadIdx.x; e < 32768; e += blockDim.x) {
        int n = e >> 9, k = e & 511;
        int s = k >> 4, kl = k & 15;
        int P = s >> 1, sp = s & 1;
        int pp = p_of_kl(kl);
        int idx = (P * 64 + n) * 32 + (pp >> 2) * 8 + sp * 4 + (pp & 3);
        g_x[dst + idx] = __float2half_rn(src[n * 512 + k]);
    }
}

// ---------------- main persistent kernel ----------------
__global__ void __launch_bounds__(NTHR, 1)
lstm_mma(const float* __restrict__ bh, float* __restrict__ out)
{
    extern __shared__ __align__(16) char smem[];
    const int tid = threadIdx.x;
    const int L = tid & 31, warp = tid >> 5;
    const int p  = warp & 3;            // batch group 0..3
    const int kh = warp >> 2;           // k-half: 0 = input, 1 = recurrent
    const int cta = blockIdx.x, layer = cta >> 6, hb = cta & 63;

    // ---- resident weight load (once) ----
    {
        const char* wsrc = (const char*)(g_w + (size_t)cta * 32768);
        for (int i = tid; i < 4096; i += NTHR)
            cp_async16(smem + SO_W + i * 16, wsrc + i * 16);
        CP_COMMIT();
    }
    float* bias_s = (float*)(smem + SO_BIAS);
    if (tid < 32)
        bias_s[tid] = bh[layer * 2048 + (tid >> 3) * 512 + hb * 8 + (tid & 7)];
    CP_WAIT(0);
    __syncthreads();

    // epilogue constants
    const int j  = L >> 2;                 // hidden within CTA (0..7)
    const int hh = hb * 8 + j;             // global hidden index
    const int pH = p_of_kl(hh & 15);
    const int hP = hh >> 5, hsp = (hh >> 4) & 1;
    const int hoff = hP * 64 * 32 + (pH >> 2) * 8 + hsp * 4 + (pH & 3);
    const float bi = bias_s[j],      bf = bias_s[8 + j];
    const float bg = bias_s[16 + j], bo = bias_s[24 + j];

    float c_st[4] = {0.f, 0.f, 0.f, 0.f};
    float h_st[4] = {0.f, 0.f, 0.f, 0.f};

    const int n0 = (p << 4) + (L >> 2);    // act row for nb=0
    const char* wbase = smem + SO_W;
    float* red = (float*)(smem + SO_RED);  // [p][L][17] floats

    // per-lane byte offset inside a 64KB paired act plane
    const int aoff = n0 * 64 + (L & 3) * 16;

    for (int w = 0; w <= TSTEPS; ++w) {
        const bool active = (layer == 0) ? (w < TSTEPS) : (w >= 1);
        if (active) {
            const int t = (layer == 0) ? w : (w - 1);

            // ---- team barrier / dependency wait ----
            if (tid == 0) {
                if (layer == 0) {
                    const unsigned tgt = 64u * (unsigned)w;
                    while (*(volatile unsigned*)&g_done0 < tgt) { }
                } else {
                    const unsigned tgt0 = 64u * (unsigned)w;        // h0[t] ready
                    while (*(volatile unsigned*)&g_done0 < tgt0) { }
                    const unsigned tgt1 = 64u * (unsigned)(w - 1);  // own team
                    while (*(volatile unsigned*)&g_done1 < tgt1) { }
                }
                __threadfence();
            }
            __syncthreads();

            const __half *Asrc, *Bsrc;
            if (layer == 0) {
                Asrc = g_x + (size_t)t * 32768;
                Bsrc = g_h0 + (size_t)(t > 0 ? t - 1 : 0) * 32768;
            } else {
                Asrc = g_h0 + (size_t)t * 32768;
                Bsrc = g_h1 + (size_t)((t - 1) & 1) * 32768;
            }
            // this warp's compute enable (recurrent half is zero at t==0)
            const bool do_mma = (kh == 0) || (t != 0);

            float d[2][2][4];
            #pragma unroll
            for (int mb = 0; mb < 2; ++mb)
                #pragma unroll
                for (int nb = 0; nb < 2; ++nb)
                    #pragma unroll
                    for (int q = 0; q < 4; ++q) d[mb][nb][q] = 0.f;

            if (do_mma) {
                const char* ag = (const char*)(kh ? Bsrc : Asrc) + aoff;

                // A register pipeline, depth 4 PAIRS (LDG.128 direct from L2)
                uint4 AP0[4], AP1[4];
                #pragma unroll
                for (int i = 0; i < 4; ++i) {
                    AP0[i] = *(const uint4*)(ag + i * 4096);
                    AP1[i] = *(const uint4*)(ag + i * 4096 + 512);
                }
                // W double buffer (4 tiles per pair) from SMEM
                uint4 WB[2][4];
                {
                    const int tb = (kh << 6);
                    #pragma unroll
                    for (int q = 0; q < 4; ++q)
                        WB[0][q] = *(const uint4*)(wbase + (size_t)(tb + q) * 512 + L * 16);
                }

                #pragma unroll
                for (int P = 0; P < 16; ++P) {
                    const int cur = P & 1;
                    if (P < 15) {
                        const int tb = (kh << 6) + (P + 1) * 4;
                        #pragma unroll
                        for (int q = 0; q < 4; ++q)
                            WB[cur ^ 1][q] = *(const uint4*)(wbase + (size_t)(tb + q) * 512 + L * 16);
                    }
                    const uint4 a0 = AP0[P & 3], a1 = AP1[P & 3];
                    if (P + 4 < 16) {
                        AP0[P & 3] = *(const uint4*)(ag + (P + 4) * 4096);
                        AP1[P & 3] = *(const uint4*)(ag + (P + 4) * 4096 + 512);
                    }
                    const uint4 w0 = WB[cur][0], w1 = WB[cur][1];
                    const uint4 w2 = WB[cur][2], w3 = WB[cur][3];

                    // kstep 2P
                    mma16816(d[0][0], w0.x, w0.y, w0.z, w0.w, a0.x, a0.y);
                    mma16816(d[0][1], w0.x, w0.y, w0.z, w0.w, a1.x, a1.y);
                    mma16816(d[1][0], w1.x, w1.y, w1.z, w1.w, a0.x, a0.y);
                    mma16816(d[1][1], w1.x, w1.y, w1.z, w1.w, a1.x, a1.y);
                    // kstep 2P+1
                    mma16816(d[0][0], w2.x, w2.y, w2.z, w2.w, a0.z, a0.w);
                    mma16816(d[0][1], w2.x, w2.y, w2.z, w2.w, a1.z, a1.w);
                    mma16816(d[1][0], w3.x, w3.y, w3.z, w3.w, a0.z, a0.w);
                    mma16816(d[1][1], w3.x, w3.y, w3.z, w3.w, a1.z, a1.w);
                }
            }

            // ---- epilogue: kh=1 stages partial D; kh=0 reduces + gates ----
            {
                float* r = red + ((p << 5) + L) * 17;
                if (kh == 1) {
                    #pragma unroll
                    for (int mb = 0; mb < 2; ++mb)
                        #pragma unroll
                        for (int nb = 0; nb < 2; ++nb)
                            #pragma unroll
                            for (int q = 0; q < 4; ++q)
                                r[(mb * 2 + nb) * 4 + q] = d[mb][nb][q];
                }
                __syncthreads();
                if (kh == 0) {
                    __half* dh = (layer == 0) ? (g_h0 + (size_t)t * 32768)
                                              : (g_h1 + (size_t)(t & 1) * 32768);
                    float* orow = out + (size_t)t * BH;
                    #pragma unroll
                    for (int nb = 0; nb < 2; ++nb) {
                        #pragma unroll
                        for (int cc = 0; cc < 2; ++cc) {
                            const int si = nb * 2 + cc;
                            const int b  = (p << 4) + (nb << 3) + ((L & 3) << 1) + cc;
                            float pi = d[0][nb][cc]     + r[nb * 4 + cc]           + bi;
                            float pf = d[0][nb][2 + cc] + r[nb * 4 + 2 + cc]       + bf;
                            float pg = d[1][nb][cc]     + r[(2 + nb) * 4 + cc]     + bg;
                            float po = d[1][nb][2 + cc] + r[(2 + nb) * 4 + 2 + cc] + bo;
                            float ig = __fdividef(1.f, 1.f + __expf(-pi));
                            float fg = __fdividef(1.f, 1.f + __expf(-pf));
                            float gt = 2.f * __fdividef(1.f, 1.f + __expf(-2.f * pg)) - 1.f;
                            float og = __fdividef(1.f, 1.f + __expf(-po));
                            float cn = fg * c_st[si] + ig * gt;
                            c_st[si] = cn;
                            float th = 2.f * __fdividef(1.f, 1.f + __expf(-2.f * cn)) - 1.f;
                            float hn = og * th;
                            h_st[si] = hn;
                            dh[hoff + b * 32] = __float2half_rn(hn);
                            if (layer == 1) orow[b * 512 + hh] = hn;
                        }
                    }
                }
            }

            // ---- publish: all stores visible, bump own team counter ----
            __threadfence();
            __syncthreads();
            if (tid == 0) {
                if (layer == 0) atomicAdd(&g_done0, 1u);
                else            atomicAdd(&g_done1, 1u);
            }
        }
    }

    // ---- final h, c tails: out layout = [out | h(L,B,H) | c(L,B,H)] ----
    if (kh == 0) {
        const size_t base = (size_t)TSTEPS * BH;
        #pragma unroll
        for (int nb = 0; nb < 2; ++nb)
            #pragma unroll
            for (int cc = 0; cc < 2; ++cc) {
                const int si = nb * 2 + cc;
                const int b  = (p << 4) + (nb << 3) + ((L & 3) << 1) + cc;
                out[base + (size_t)layer * BH + (size_t)b * 512 + hh] = h_st[si];
                out[base + 2 * (size_t)BH + (size_t)layer * BH + (size_t)b * 512 + hh] = c_st[si];
            }
    }

    // replay safety: all CTAs done -> reset team counters
    grid_sync();
    if (cta == 0 && tid == 0) { g_done0 = 0; g_done1 = 0; }
}

extern "C" void kernel_launch(void* const* d_in, const int* in_sizes, int n_in,
                              void* d_out, int out_size) {
    (void)in_sizes; (void)n_in; (void)out_size;
    const float* x  = (const float*)d_in[0];
    const float* Wx = (const float*)d_in[1];
    const float* Wh = (const float*)d_in[2];
    const float* bh = (const float*)d_in[3];
    float* out = (float*)d_out;

    prep_w<<<NCTA * 8, 128>>>(Wx, Wh);
    prep_x<<<TSTEPS, 256>>>(x);

    cudaFuncSetAttribute(lstm_mma, cudaFuncAttributeMaxDynamicSharedMemorySize,
                         SMEM_TOTAL);
    lstm_mma<<<NCTA, NTHR, SMEM_TOTAL>>>(bh, out);
}

// round 17
// speedup vs baseline: 1.1477x; 1.1477x over previous
#include <cuda_runtime.h>
#include <cuda_fp16.h>
#include <cstdint>

// ---------------------------------------------------------------------------
// LSTM_41764261986630 : 2-layer LSTM, T=512, B=64, IN=H=512
// mma.sync (HMMA) single-term fp16, persistent, weight-stationary.
// R16: R15's warp-group decoupling, rebuilt on monotonic SMEM counters
// (named-barrier phase aliasing caused R15's deadlock).
//   kh=0 warps: input half, up to 2 waves ahead, double-buffered deposits.
//   kh=1 warps: recurrent half + reduce + gates + publish.
//   dep_cnt / cons_cnt (smem) pair the groups; global per-team counters
//   pair the CTAs.  No __syncthreads in the wave loop.
// ---------------------------------------------------------------------------

#define TSTEPS 512
#define BATCH  64
#define HID    512
#define BH     (BATCH*HID)
#define NCTA   128
#define NTHR   256

// SMEM byte offsets
#define SO_W    0          // 65536 B : [tile 0..127][256 fp16]
#define SO_RED  65536      // 2 x 4*32*17*4 = 17408 B partial-D staging
#define SO_BIAS 82944      // 32 floats
#define SO_CNT  83072      // 2 unsigned counters (dep, cons)
#define SMEM_TOTAL 83200

// ---- persistent device scratch (no cudaMalloc allowed) ----
__device__ __align__(16) __half g_w[(size_t)NCTA*128*256];          // 8MB
__device__ __align__(16) __half g_x[(size_t)TSTEPS*32768];          // 32MB
__device__ __align__(16) __half g_h0[(size_t)TSTEPS*32768];         // full depth
__device__ __align__(16) __half g_h1[2*32768];
__device__ unsigned g_bar;
__device__ unsigned g_done0, g_done1;    // per-team counters (4 warps/CTA/wave)

// ---------------- helpers ----------------
__device__ __forceinline__ void cp_async16(void* sdst, const void* gsrc) {
    unsigned sa;
    asm("{ .reg .u64 t; cvta.to.shared.u64 t, %1; cvt.u32.u64 %0, t; }"
        : "=r"(sa) : "l"(sdst));
    asm volatile("cp.async.cg.shared.global [%0], [%1], 16;\n" :: "r"(sa), "l"(gsrc));
}
#define CP_COMMIT() asm volatile("cp.async.commit_group;\n")
#define CP_WAIT(n)  asm volatile("cp.async.wait_group %0;\n" :: "n"(n))

__device__ __forceinline__ void mma16816(float* d,
        uint32_t a0, uint32_t a1, uint32_t a2, uint32_t a3,
        uint32_t b0, uint32_t b1) {
    asm volatile(
      "mma.sync.aligned.m16n8k16.row.col.f32.f16.f16.f32 "
      "{%0,%1,%2,%3}, {%4,%5,%6,%7}, {%8,%9}, {%0,%1,%2,%3};"
      : "+f"(d[0]), "+f"(d[1]), "+f"(d[2]), "+f"(d[3])
      : "r"(a0), "r"(a1), "r"(a2), "r"(a3), "r"(b0), "r"(b1));
}

// fragment-order position of k-local element within a 16-wide act row
__device__ __host__ __forceinline__ int p_of_kl(int kl) {
    return ((kl & 7) >> 1) * 4 + ((kl >> 3) << 1) + (kl & 1);
}

// warp-uniform acquire poll on a global counter
__device__ __forceinline__ void poll_ge(unsigned* ctr, unsigned tgt) {
    while (*(volatile unsigned*)ctr < tgt) { }
    __threadfence();
}

// final full-grid barrier (monotonic counter: safe across graph replays)
__device__ __forceinline__ void grid_sync() {
    __threadfence();
    __syncthreads();
    if (threadIdx.x == 0) {
        unsigned arrive = atomicAdd(&g_bar, 1u);
        unsigned target = (arrive / NCTA + 1u) * NCTA;
        while (*(volatile unsigned*)&g_bar < target) { }
        __threadfence();
    }
    __syncthreads();
}

// ---------------- prep kernels ----------------
// W fragment image per CTA: [tile ti = s*2+mb][lane L][8 fp16]
__global__ void prep_w(const float* __restrict__ Wx, const float* __restrict__ Wh) {
    const int blk = blockIdx.x;               // cta*8 + ch
    const int ch = blk & 7, cta = blk >> 3;
    const int layer = cta >> 6, hb = cta & 63;
    const float* wx = Wx + (size_t)layer * 2048 * 512;
    const float* wh = Wh + (size_t)layer * 2048 * 512;
    const size_t base = (size_t)cta * 128 * 256;
    for (int e = threadIdx.x; e < 16 * 256; e += blockDim.x) {
        int ti  = ch * 16 + (e >> 8);
        int q16 = e & 255;
        int L = q16 >> 3, eb = q16 & 7;
        int qreg = eb >> 1, half = eb & 1;
        int s = ti >> 1, mb = ti & 1;
        int m  = (L >> 2) + ((qreg & 1) << 3) + (mb << 4);   // row 0..31
        int kl = ((L & 3) << 1) + ((qreg >> 1) << 3) + half;
        int k  = (s << 4) + kl;
        int R  = (m >> 3) * 512 + hb * 8 + (m & 7);
        float v = (k < 512) ? wx[(size_t)R * 512 + k]
                            : wh[(size_t)R * 512 + (k - 512)];
        g_w[base + (size_t)ti * 256 + q16] = __float2half_rn(v);
    }
}

// x fragment image, PAIRED layout:
// [t][pair P 0..15][n 0..63][lane-quad 0..3][sp 0..1][half 0..3]
__global__ void prep_x(const float* __restrict__ x) {
    const int t = blockIdx.x;
    const float* src = x + (size_t)t * BH;
    const size_t dst = (size_t)t * 32768;
    for (int e = threadIdx.x; e < 32768; e += blockDim.x) {
        int n = e >> 9, k = e & 511;
        int s = k >> 4, kl = k & 15;
        int P = s >> 1, sp = s & 1;
        int pp = p_of_kl(kl);
        int idx = (P * 64 + n) * 32 + (pp >> 2) * 8 + sp * 4 + (pp & 3);
        g_x[dst + idx] = __float2half_rn(src[n * 512 + k]);
    }
}

// ---------------- main persistent kernel ----------------
__global__ void __launch_bounds__(NTHR, 1)
lstm_mma(const float* __restrict__ bh, float* __restrict__ out)
{
    extern __shared__ __align__(16) char smem[];
    const int tid = threadIdx.x;
    const int L = tid & 31, warp = tid >> 5;
    const int p  = warp & 3;            // batch group 0..3
    const int kh = warp >> 2;           // 0 = input group, 1 = recurrent group
    const int cta = blockIdx.x, layer = cta >> 6, hb = cta & 63;

    volatile unsigned* dep_cnt  = (volatile unsigned*)(smem + SO_CNT);
    volatile unsigned* cons_cnt = (volatile unsigned*)(smem + SO_CNT + 4);
    unsigned* dep_a  = (unsigned*)(smem + SO_CNT);
    unsigned* cons_a = (unsigned*)(smem + SO_CNT + 4);

    // ---- resident weight load (once) ----
    {
        const char* wsrc = (const char*)(g_w + (size_t)cta * 32768);
        for (int i = tid; i < 4096; i += NTHR)
            cp_async16(smem + SO_W + i * 16, wsrc + i * 16);
        CP_COMMIT();
    }
    float* bias_s = (float*)(smem + SO_BIAS);
    if (tid < 32)
        bias_s[tid] = bh[layer * 2048 + (tid >> 3) * 512 + hb * 8 + (tid & 7)];
    if (tid == 0) { *dep_a = 0; *cons_a = 0; }
    CP_WAIT(0);
    __syncthreads();

    // epilogue constants
    const int j  = L >> 2;                 // hidden within CTA (0..7)
    const int hh = hb * 8 + j;             // global hidden index
    const int pH = p_of_kl(hh & 15);
    const int hP = hh >> 5, hsp = (hh >> 4) & 1;
    const int hoff = hP * 64 * 32 + (pH >> 2) * 8 + hsp * 4 + (pH & 3);
    const float bi = bias_s[j],      bf = bias_s[8 + j];
    const float bg = bias_s[16 + j], bo = bias_s[24 + j];

    float c_st[4] = {0.f, 0.f, 0.f, 0.f};
    float h_st[4] = {0.f, 0.f, 0.f, 0.f};

    const int n0 = (p << 4) + (L >> 2);    // act row for nb=0
    const char* wbase = smem + SO_W;
    float* red = (float*)(smem + SO_RED);  // [buf][p][L][17] floats

    // per-lane byte offset inside a 64KB paired act plane
    const int aoff = n0 * 64 + (L & 3) * 16;

    unsigned* ownctr = layer ? &g_done1 : &g_done0;

    for (int w = 0; w <= TSTEPS; ++w) {
        const bool active = (layer == 0) ? (w < TSTEPS) : (w >= 1);
        if (!active) continue;
        const int t = (layer == 0) ? w : (w - 1);
        const int buf = t & 1;

        float d[2][2][4];
        #pragma unroll
        for (int mb = 0; mb < 2; ++mb)
            #pragma unroll
            for (int nb = 0; nb < 2; ++nb)
                #pragma unroll
                for (int q = 0; q < 4; ++q) d[mb][nb][q] = 0.f;

        // ---- MMA body (this warp's k-half) ----
        auto mma_half = [&](const char* ag) {
            uint4 AP0[4], AP1[4];
            #pragma unroll
            for (int i = 0; i < 4; ++i) {
                AP0[i] = *(const uint4*)(ag + i * 4096);
                AP1[i] = *(const uint4*)(ag + i * 4096 + 512);
            }
            uint4 WB[2][4];
            {
                const int tb = (kh << 6);
                #pragma unroll
                for (int q = 0; q < 4; ++q)
                    WB[0][q] = *(const uint4*)(wbase + (size_t)(tb + q) * 512 + L * 16);
            }
            #pragma unroll
            for (int P = 0; P < 16; ++P) {
                const int cur = P & 1;
                if (P < 15) {
                    const int tb = (kh << 6) + (P + 1) * 4;
                    #pragma unroll
                    for (int q = 0; q < 4; ++q)
                        WB[cur ^ 1][q] = *(const uint4*)(wbase + (size_t)(tb + q) * 512 + L * 16);
                }
                const uint4 a0 = AP0[P & 3], a1 = AP1[P & 3];
                if (P + 4 < 16) {
                    AP0[P & 3] = *(const uint4*)(ag + (P + 4) * 4096);
                    AP1[P & 3] = *(const uint4*)(ag + (P + 4) * 4096 + 512);
                }
                const uint4 w0 = WB[cur][0], w1 = WB[cur][1];
                const uint4 w2 = WB[cur][2], w3 = WB[cur][3];
                mma16816(d[0][0], w0.x, w0.y, w0.z, w0.w, a0.x, a0.y);
                mma16816(d[0][1], w0.x, w0.y, w0.z, w0.w, a1.x, a1.y);
                mma16816(d[1][0], w1.x, w1.y, w1.z, w1.w, a0.x, a0.y);
                mma16816(d[1][1], w1.x, w1.y, w1.z, w1.w, a1.x, a1.y);
                mma16816(d[0][0], w2.x, w2.y, w2.z, w2.w, a0.z, a0.w);
                mma16816(d[0][1], w2.x, w2.y, w2.z, w2.w, a1.z, a1.w);
                mma16816(d[1][0], w3.x, w3.y, w3.z, w3.w, a0.z, a0.w);
                mma16816(d[1][1], w3.x, w3.y, w3.z, w3.w, a1.z, a1.w);
            }
        };

        if (kh == 0) {
            // -------- input-half group (no own-team dependency) --------
            if (layer == 1)
                poll_ge(&g_done0, 256u * (unsigned)w);    // h0[t] ready
            if (t >= 2)
                while (*cons_cnt < 4u * (unsigned)(t - 1)) { }  // buf free
            const __half* Asrc = (layer == 0) ? (g_x  + (size_t)t * 32768)
                                              : (g_h0 + (size_t)t * 32768);
            mma_half((const char*)Asrc + aoff);
            // deposit partials
            float* r = red + ((size_t)(buf * 128 + (p << 5) + L)) * 17;
            #pragma unroll
            for (int mb = 0; mb < 2; ++mb)
                #pragma unroll
                for (int nb = 0; nb < 2; ++nb)
                    #pragma unroll
                    for (int q = 0; q < 4; ++q)
                        r[(mb * 2 + nb) * 4 + q] = d[mb][nb][q];
            __threadfence_block();
            __syncwarp();
            if (L == 0) atomicAdd(dep_a, 1u);
        } else {
            // -------- recurrent-half group (serial chain) --------
            if (t > 0) {
                const unsigned tgt = (layer == 0) ? 256u * (unsigned)w
                                                  : 256u * (unsigned)(w - 1);
                poll_ge(ownctr, tgt);
                const __half* Bsrc = (layer == 0)
                    ? (g_h0 + (size_t)(t - 1) * 32768)
                    : (g_h1 + (size_t)((t - 1) & 1) * 32768);
                mma_half((const char*)Bsrc + aoff);
            }
            // wait for kh0's deposit of wave t
            while (*dep_cnt < 4u * (unsigned)(t + 1)) { }
            __threadfence_block();

            const float* r = red + ((size_t)(buf * 128 + (p << 5) + L)) * 17;
            __half* dh = (layer == 0) ? (g_h0 + (size_t)t * 32768)
                                      : (g_h1 + (size_t)(t & 1) * 32768);
            float* orow = out + (size_t)t * BH;
            #pragma unroll
            for (int nb = 0; nb < 2; ++nb) {
                #pragma unroll
                for (int cc = 0; cc < 2; ++cc) {
                    const int si = nb * 2 + cc;
                    const int b  = (p << 4) + (nb << 3) + ((L & 3) << 1) + cc;
                    float pi = d[0][nb][cc]     + r[nb * 4 + cc]           + bi;
                    float pf = d[0][nb][2 + cc] + r[nb * 4 + 2 + cc]       + bf;
                    float pg = d[1][nb][cc]     + r[(2 + nb) * 4 + cc]     + bg;
                    float po = d[1][nb][2 + cc] + r[(2 + nb) * 4 + 2 + cc] + bo;
                    float ig = __fdividef(1.f, 1.f + __expf(-pi));
                    float fg = __fdividef(1.f, 1.f + __expf(-pf));
                    float gt = 2.f * __fdividef(1.f, 1.f + __expf(-2.f * pg)) - 1.f;
                    float og = __fdividef(1.f, 1.f + __expf(-po));
                    float cn = fg * c_st[si] + ig * gt;
                    c_st[si] = cn;
                    float th = 2.f * __fdividef(1.f, 1.f + __expf(-2.f * cn)) - 1.f;
                    float hn = og * th;
                    h_st[si] = hn;
                    dh[hoff + b * 32] = __float2half_rn(hn);
                    if (layer == 1) orow[b * 512 + hh] = hn;
                }
            }
            // partials consumed -> free the buffer for kh0
            __threadfence_block();
            __syncwarp();
            if (L == 0) atomicAdd(cons_a, 1u);
            // publish h to other CTAs
            __threadfence();
            __syncwarp();
            if (L == 0) atomicAdd(ownctr, 1u);
        }
    }

    // ---- final h, c tails: out layout = [out | h(L,B,H) | c(L,B,H)] ----
    if (kh == 1) {
        const size_t base = (size_t)TSTEPS * BH;
        #pragma unroll
        for (int nb = 0; nb < 2; ++nb)
            #pragma unroll
            for (int cc = 0; cc < 2; ++cc) {
                const int si = nb * 2 + cc;
                const int b  = (p << 4) + (nb << 3) + ((L & 3) << 1) + cc;
                out[base + (size_t)layer * BH + (size_t)b * 512 + hh] = h_st[si];
                out[base + 2 * (size_t)BH + (size_t)layer * BH + (size_t)b * 512 + hh] = c_st[si];
            }
    }

    // replay safety: all CTAs done -> reset team counters
    grid_sync();
    if (cta == 0 && tid == 0) { g_done0 = 0; g_done1 = 0; }
}

extern "C" void kernel_launch(void* const* d_in, const int* in_sizes, int n_in,
                              void* d_out, int out_size) {
    (void)in_sizes; (void)n_in; (void)out_size;
    const float* x  = (const float*)d_in[0];
    const float* Wx = (const float*)d_in[1];
    const float* Wh = (const float*)d_in[2];
    const float* bh = (const float*)d_in[3];
    float* out = (float*)d_out;

    prep_w<<<NCTA * 8, 128>>>(Wx, Wh);
    prep_x<<<TSTEPS, 256>>>(x);

    cudaFuncSetAttribute(lstm_mma, cudaFuncAttributeMaxDynamicSharedMemorySize,
                         SMEM_TOTAL);
    lstm_mma<<<NCTA, NTHR, SMEM_TOTAL>>>(bh, out);
}